// round 14
// baseline (speedup 1.0000x reference)
#include <cuda_runtime.h>
#include <cuda_fp16.h>
#include <stdint.h>

// ===========================================================================
// Helpers
// ===========================================================================
__device__ __forceinline__ uint32_t smem_to_u32(const void* p) {
    uint32_t a;
    asm("{ .reg .u64 t; cvta.to.shared.u64 t, %1; cvt.u32.u64 %0, t; }" : "=r"(a) : "l"(p));
    return a;
}
__device__ __forceinline__ void cp_async16(uint32_t saddr, const void* gptr) {
    asm volatile("cp.async.cg.shared.global [%0], [%1], 16;" :: "r"(saddr), "l"(gptr));
}
#define CP_COMMIT() asm volatile("cp.async.commit_group;" ::: "memory")
template <int N>
__device__ __forceinline__ void cp_wait() {
    asm volatile("cp.async.wait_group %0;" :: "n"(N) : "memory");
}

__device__ __forceinline__ void ldx4(uint32_t* r, uint32_t addr) {
    asm volatile("ldmatrix.sync.aligned.m8n8.x4.shared.b16 {%0,%1,%2,%3}, [%4];"
                 : "=r"(r[0]), "=r"(r[1]), "=r"(r[2]), "=r"(r[3]) : "r"(addr));
}
__device__ __forceinline__ void mma16(float* d, const uint32_t* a, const uint32_t* b) {
    asm volatile(
        "mma.sync.aligned.m16n8k16.row.col.f32.f16.f16.f32 "
        "{%0,%1,%2,%3}, {%4,%5,%6,%7}, {%8,%9}, {%0,%1,%2,%3};"
        : "+f"(d[0]), "+f"(d[1]), "+f"(d[2]), "+f"(d[3])
        : "r"(a[0]), "r"(a[1]), "r"(a[2]), "r"(a[3]), "r"(b[0]), "r"(b[1]));
}
__device__ __forceinline__ uint32_t pack2(float a, float b) {
    __half2 h = __floats2half2_rn(a, b);
    return *reinterpret_cast<uint32_t*>(&h);
}

// ===========================================================================
// Scratch (device globals only)
// ===========================================================================
__device__ float g_act1[64 * 24 * 64 * 64];
__device__ float g_act2[64 * 24 * 32 * 32];
__device__ float g_act3[64 * 24 * 16 * 16];
__device__ float g_act4[64 * 24 * 8 * 8];
__device__ float g_bnp[24][16][2];
__device__ float g_u[4096 * 256];
__device__ float g_v[4096 * 256];
__device__ float g_qb[64 * 256];
__device__ __half g_Wt[3][256 * 256];     // W^T fp16, [n][k]
__device__ float g_part[2048 * 256];

// ===========================================================================
// Conv (3x3, stride 2, pad 1) + bias + relu.
// 4 ow x 2 co per thread, vectorized input loads, 3 CTAs/SM.
// FOLD=1: previous layer's BN folded on input load; the per-channel
// scale/shift is finalized IN-BLOCK from the 16-way partials (g_bnp).
// ===========================================================================
template <int L>
__device__ __forceinline__ float* act_buf() {
    if constexpr (L == 1) return g_act1;
    else if constexpr (L == 2) return g_act2;
    else if constexpr (L == 3) return g_act3;
    else return g_act4;
}

template <int L, int FOLD>
__global__ void __launch_bounds__(256, 3) conv_kernel(const float* __restrict__ img,
                                                      const float* __restrict__ w,
                                                      const float* __restrict__ cb,
                                                      const float* __restrict__ bg,
                                                      const float* __restrict__ bb) {
    constexpr int CIN = (L == 1) ? 3 : 24;
    constexpr int H   = 256 >> L;
    constexpr int OH  = 128 >> L;
    constexpr int OQ  = OH / 4;
    constexpr int NW  = 24 * CIN * 9;

    __shared__ float sw[NW];
    __shared__ float ssc[24], ssh[24];
    for (int i = threadIdx.x; i < NW; i += 256) sw[i] = w[i];
    if (FOLD && threadIdx.x < 24) {
        constexpr float NPREV = 64.f * (float)((256 >> L) * (256 >> L));
        int c = threadIdx.x;
        float s = 0.f, s2 = 0.f;
#pragma unroll
        for (int k = 0; k < 16; k++) { s += g_bnp[c][k][0]; s2 += g_bnp[c][k][1]; }
        float m   = s / NPREV;
        float var = s2 / NPREV - m * m;
        float rst = rsqrtf(var + 1e-5f);
        ssc[c] = rst * bg[c];
        ssh[c] = bb[c] - m * rst * bg[c];
    }
    __syncthreads();

    const float* in = (L == 1) ? img : act_buf<L - 1 + (L == 1 ? 1 : 0)>();
    float* out = act_buf<L>();

    int idx = blockIdx.x * 256 + threadIdx.x;
    int ow4 = idx % OQ; idx /= OQ;
    int oh  = idx % OH; idx /= OH;
    int cog = idx % 12; int b = idx / 12;
    if (b >= 64) return;
    const int ow0 = ow4 * 4;
    const int co0 = cog * 2;

    float acc[2][4];
#pragma unroll
    for (int c = 0; c < 2; c++) {
        float bv = cb[co0 + c];
#pragma unroll
        for (int d = 0; d < 4; d++) acc[c][d] = bv;
    }

    const int iw0 = 2 * ow0 - 1;
#pragma unroll
    for (int ci = 0; ci < CIN; ci++) {
        const float* ip = in + ((b * CIN + ci) * H) * H;
        const float sc = FOLD ? ssc[ci] : 1.f;
        const float sh = FOLD ? ssh[ci] : 0.f;
        const float* wb = &sw[(co0 * CIN + ci) * 9];
#pragma unroll
        for (int kh = 0; kh < 3; kh++) {
            int ih = 2 * oh - 1 + kh;
            bool rowok = (ih >= 0);                  // ih < H always holds
            const float* rp = ip + ih * H;
            float x[9];
            if (rowok) {
                float4 va = *reinterpret_cast<const float4*>(rp + iw0 + 1);
                float4 vb = *reinterpret_cast<const float4*>(rp + iw0 + 5);
                x[0] = (ow0 > 0) ? rp[iw0] : 0.f;
                x[1] = va.x; x[2] = va.y; x[3] = va.z; x[4] = va.w;
                x[5] = vb.x; x[6] = vb.y; x[7] = vb.z; x[8] = vb.w;
                if (FOLD) {
                    if (ow0 > 0) x[0] = fmaf(x[0], sc, sh);
#pragma unroll
                    for (int t = 1; t < 9; t++) x[t] = fmaf(x[t], sc, sh);
                }
            } else {
#pragma unroll
                for (int t = 0; t < 9; t++) x[t] = 0.f;
            }
#pragma unroll
            for (int c = 0; c < 2; c++) {
                const float* wp = wb + c * CIN * 9 + kh * 3;
#pragma unroll
                for (int kw = 0; kw < 3; kw++) {
                    float wv = wp[kw];
#pragma unroll
                    for (int d = 0; d < 4; d++)
                        acc[c][d] = fmaf(x[2 * d + kw], wv, acc[c][d]);
                }
            }
        }
    }

#pragma unroll
    for (int c = 0; c < 2; c++) {
        float4 o;
        o.x = fmaxf(acc[c][0], 0.f); o.y = fmaxf(acc[c][1], 0.f);
        o.z = fmaxf(acc[c][2], 0.f); o.w = fmaxf(acc[c][3], 0.f);
        *reinterpret_cast<float4*>(
            &out[((b * 24 + co0 + c) * OH + oh) * OH + ow0]) = o;
    }
}

// ===========================================================================
// BatchNorm partial stats (16-way, fixed order, deterministic)
// ===========================================================================
template <int L>
__global__ void bn_part_kernel() {
    constexpr int HW  = (128 >> L) * (128 >> L);
    constexpr int N   = 64 * HW;
    constexpr int SEG = N / 16;
    const float* y = act_buf<L>();
    int c = blockIdx.x, seg = blockIdx.y, t = threadIdx.x;

    float s = 0.f, s2 = 0.f;
    for (int i = seg * SEG + t; i < (seg + 1) * SEG; i += 256) {
        int b = i / HW;
        int p = i - b * HW;
        float v = y[(b * 24 + c) * HW + p];
        s += v;
        s2 += v * v;
    }
    __shared__ float rs[256], rq[256];
    rs[t] = s;
    rq[t] = s2;
    __syncthreads();
    for (int o = 128; o > 0; o >>= 1) {
        if (t < o) { rs[t] += rs[t + o]; rq[t] += rq[t + o]; }
        __syncthreads();
    }
    if (t == 0) { g_bnp[c][seg][0] = rs[0]; g_bnp[c][seg][1] = rq[0]; }
}

// ===========================================================================
// u/v/qb projections (uv finalizes + folds BN4 in-block)
// ===========================================================================
__global__ void uv_kernel(const float* __restrict__ gw1,
                          const float* __restrict__ bg4,
                          const float* __restrict__ bb4) {
    int bp = blockIdx.x;
    int b  = bp >> 6;
    int p  = bp & 63;
    int t  = threadIdx.x;

    __shared__ float ssc[24], ssh[24];
    __shared__ float o[26];
    if (t < 24) {
        float s = 0.f, s2 = 0.f;
#pragma unroll
        for (int k = 0; k < 16; k++) { s += g_bnp[t][k][0]; s2 += g_bnp[t][k][1]; }
        float m   = s / 4096.f;
        float var = s2 / 4096.f - m * m;
        float rst = rsqrtf(var + 1e-5f);
        ssc[t] = rst * bg4[t];
        ssh[t] = bb4[t] - m * rst * bg4[t];
    }
    __syncthreads();
    if (t < 24) o[t] = fmaf(g_act4[(b * 24 + t) * 64 + p], ssc[t], ssh[t]);
    else if (t == 24) o[24] = (float)(p >> 3);
    else if (t == 25) o[25] = (float)(p & 7);
    __syncthreads();

    float u = 0.f, v = 0.f;
#pragma unroll
    for (int c = 0; c < 26; c++) {
        float oc = o[c];
        u = fmaf(oc, gw1[c * 256 + t], u);
        v = fmaf(oc, gw1[(26 + c) * 256 + t], v);
    }
    g_u[bp * 256 + t] = u;
    g_v[bp * 256 + t] = v;
}

__global__ void qb_kernel(const float* __restrict__ qst,
                          const float* __restrict__ gw1,
                          const float* __restrict__ gb1) {
    int b = blockIdx.x;
    int t = threadIdx.x;
    __shared__ float q[11];
    if (t < 11) q[t] = qst[b * 11 + t];
    __syncthreads();
    float s = gb1[t];
#pragma unroll
    for (int k = 0; k < 11; k++) s = fmaf(q[k], gw1[(52 + k) * 256 + t], s);
    g_qb[b * 256 + t] = s;
}

// ===========================================================================
// W prep: transpose to [n][k], round to fp16
// ===========================================================================
__global__ void prep_w_kernel(const float* __restrict__ w2,
                              const float* __restrict__ w3,
                              const float* __restrict__ w4) {
    __shared__ float tb[32][33];
    int L = blockIdx.z;
    const float* w = (L == 0) ? w2 : (L == 1) ? w3 : w4;
    int kb = blockIdx.y * 32, nb = blockIdx.x * 32;
#pragma unroll
    for (int i = 0; i < 4; i++)
        tb[threadIdx.y + 8 * i][threadIdx.x] = w[(kb + threadIdx.y + 8 * i) * 256 + nb + threadIdx.x];
    __syncthreads();
#pragma unroll
    for (int i = 0; i < 4; i++) {
        int n = nb + threadIdx.y + 8 * i;
        int k = kb + threadIdx.x;
        g_Wt[L][n * 256 + k] = __float2half_rn(tb[threadIdx.x][threadIdx.y + 8 * i]);
    }
}

// ===========================================================================
// FUSED relation MLP v5: 128-row tile, h1 -> h2 -> h3 -> column sums.
// h tile (64KB, fp16, swizzled) updated IN PLACE at layer boundaries.
// K-chunk = 64, 5-stage B ring (32KB stages), prefetch depth 4, wait<=3.
// CTA: 128 rows x 256 cols, 512 threads (16 warps, 2M x 8N, warp 64x32).
// ===========================================================================
static constexpr int BOFF = 65536, BSTAGE = 32768;          // B ring: 5 x 32KB
static constexpr int GEMM_SMEM = BOFF + 5 * BSTAGE;         // 224KB

__global__ void __launch_bounds__(512, 1) rn_fused(const float* __restrict__ gb2,
                                                   const float* __restrict__ gb3,
                                                   const float* __restrict__ gb4) {
    extern __shared__ char smem[];
    const uint32_t sb = smem_to_u32(smem);

    const int tid  = threadIdx.x;
    const int lane = tid & 31;
    const int wid  = tid >> 5;           // 0..15
    const int g    = lane >> 2;
    const int tig  = lane & 3;
    const int warpM = wid & 1;
    const int warpN = wid >> 1;          // 0..7
    const int m0 = blockIdx.x << 7;

    // ---- per-lane ldmatrix geometry ----
    const int arow16 = lane & 15;
    const int ca = (lane >> 4) & 1;      // k-half (16B)
    const int rxa = lane & 7;            // swizzle phase (row & 7)
    uint32_t rowbA[4];
#pragma unroll
    for (int i = 0; i < 4; i++)
        rowbA[i] = (uint32_t)(warpM * 64 + i * 16 + arow16) * 512;

    uint32_t offB[2][4];
    {
        int rb = (lane & 7) + ((lane >> 4) & 1) * 8;
        int cbs = (lane >> 3) & 1;
#pragma unroll
        for (int jp = 0; jp < 2; jp++)
#pragma unroll
            for (int ks = 0; ks < 4; ks++) {
                int row = warpN * 32 + jp * 16 + rb;
                int ch  = 2 * ks + cbs;
                offB[jp][ks] = BOFF + row * 128 + ((ch ^ (row & 7)) << 4);
            }
    }

    // ---- B prefetch: chunk gidx (64 k's) -> ring stage gidx % 5 ----
    auto issueB = [&](int gidx) {
        int l = gidx >> 2, kt = gidx & 3, st = gidx % 5;
        int row = tid >> 1;              // 0..255
        const __half* src = g_Wt[l] + row * 256 + kt * 64;
        uint32_t dbase = sb + BOFF + st * BSTAGE + row * 128;
        int rsw = row & 7;
#pragma unroll
        for (int cc = 0; cc < 4; cc++) {
            int c = 4 * (tid & 1) + cc;
            cp_async16(dbase + ((c ^ rsw) << 4), src + 8 * c);
        }
        CP_COMMIT();
    };
    issueB(0); issueB(1); issueB(2); issueB(3);

    // ---- build h1 tile (128 rows) while prefetches fly ----
    {
        int row = tid >> 2, kq = tid & 3;
        int rg = m0 + row;
        int b = rg >> 12, ii = (rg >> 6) & 63, jj = rg & 63;
        const float* up = g_u + ((b << 6) + jj) * 256;
        const float* vp = g_v + ((b << 6) + ii) * 256;
        const float* qp = g_qb + (b << 8);
        uint32_t rbase = row * 512;
        int rx = row & 7;
#pragma unroll
        for (int q = 0; q < 8; q++) {
            int s = kq + 4 * q;
            int k0 = s * 8;
            uint32_t ph[4];
#pragma unroll
            for (int h = 0; h < 2; h++) {
                float4 uu = *reinterpret_cast<const float4*>(up + k0 + 4 * h);
                float4 vv = *reinterpret_cast<const float4*>(vp + k0 + 4 * h);
                float4 qq = *reinterpret_cast<const float4*>(qp + k0 + 4 * h);
                float x0 = fmaxf(uu.x + vv.x + qq.x, 0.f);
                float x1 = fmaxf(uu.y + vv.y + qq.y, 0.f);
                float x2 = fmaxf(uu.z + vv.z + qq.z, 0.f);
                float x3 = fmaxf(uu.w + vv.w + qq.w, 0.f);
                ph[2 * h]     = pack2(x0, x1);
                ph[2 * h + 1] = pack2(x2, x3);
            }
            *reinterpret_cast<uint4*>(smem + rbase + ((s ^ rx) << 4)) =
                make_uint4(ph[0], ph[1], ph[2], ph[3]);
        }
    }

    float acc[4][4][4];
    float bz[4][2];
    const float* biases[3] = {gb2, gb3, gb4};

    for (int gidx = 0; gidx < 12; gidx++) {
        const int l  = gidx >> 2;
        const int kt = gidx & 3;
        const int st = gidx % 5;

        if (gidx <= 8) cp_wait<3>();
        else if (gidx == 9) cp_wait<2>();
        else if (gidx == 10) cp_wait<1>();
        else cp_wait<0>();
        __syncthreads();
        if (gidx < 8) issueB(gidx + 4);

        if (kt == 0) {
            const float* bp = biases[l];
#pragma unroll
            for (int j = 0; j < 4; j++) {
                int c = warpN * 32 + j * 8 + 2 * tig;
                bz[j][0] = bp[c];
                bz[j][1] = bp[c + 1];
            }
#pragma unroll
            for (int i = 0; i < 4; i++)
#pragma unroll
                for (int j = 0; j < 4; j++)
#pragma unroll
                    for (int e = 0; e < 4; e++) acc[i][j][e] = 0.f;
        }

        // ---- compute chunk (64 k's = 4 x k16) ----
#pragma unroll
        for (int ks = 0; ks < 4; ks++) {
            uint32_t bf[2][4];
#pragma unroll
            for (int jp = 0; jp < 2; jp++)
                ldx4(bf[jp], sb + st * BSTAGE + offB[jp][ks]);
            const int slot = kt * 8 + ks * 2 + ca;
            const uint32_t soff = (uint32_t)((slot ^ rxa) << 4);
#pragma unroll
            for (int i = 0; i < 4; i++) {
                uint32_t af[4];
                ldx4(af, sb + rowbA[i] + soff);
#pragma unroll
                for (int jp = 0; jp < 2; jp++) {
                    mma16(acc[i][2 * jp],     af, bf[jp]);
                    mma16(acc[i][2 * jp + 1], af, bf[jp] + 2);
                }
            }
        }

        // ---- layer epilogue ----
        if (kt == 3) {
            __syncthreads();   // all reads of this layer's h done before overwrite
            if (l < 2) {
#pragma unroll
                for (int i = 0; i < 4; i++) {
                    int r0 = warpM * 64 + i * 16 + g;
                    int r1 = r0 + 8;
#pragma unroll
                    for (int j = 0; j < 4; j++) {
                        int cbyte = warpN * 64 + j * 16 + tig * 4;
                        int s = cbyte >> 4, off = cbyte & 15;
                        float y00 = fmaxf(acc[i][j][0] + bz[j][0], 0.f);
                        float y01 = fmaxf(acc[i][j][1] + bz[j][1], 0.f);
                        float y10 = fmaxf(acc[i][j][2] + bz[j][0], 0.f);
                        float y11 = fmaxf(acc[i][j][3] + bz[j][1], 0.f);
                        *reinterpret_cast<uint32_t*>(
                            smem + r0 * 512 + ((s ^ (r0 & 7)) << 4) + off) =
                            pack2(y00, y01);
                        *reinterpret_cast<uint32_t*>(
                            smem + r1 * 512 + ((s ^ (r1 & 7)) << 4) + off) =
                            pack2(y10, y11);
                    }
                }
                // next chunk's syncthreads orders these writes before reads
            } else {
                // final layer: fused 128-row column sums -> g_part
                float* red = reinterpret_cast<float*>(smem);  // h tile dead
#pragma unroll
                for (int j = 0; j < 4; j++) {
                    float s0 = 0.f, s1 = 0.f;
#pragma unroll
                    for (int i = 0; i < 4; i++) {
                        s0 += fmaxf(acc[i][j][0] + bz[j][0], 0.f) +
                              fmaxf(acc[i][j][2] + bz[j][0], 0.f);
                        s1 += fmaxf(acc[i][j][1] + bz[j][1], 0.f) +
                              fmaxf(acc[i][j][3] + bz[j][1], 0.f);
                    }
#pragma unroll
                    for (int m = 4; m <= 16; m <<= 1) {
                        s0 += __shfl_xor_sync(0xffffffffu, s0, m);
                        s1 += __shfl_xor_sync(0xffffffffu, s1, m);
                    }
                    if (lane < 4) {
                        red[warpM * 256 + warpN * 32 + j * 8 + 2 * lane]     = s0;
                        red[warpM * 256 + warpN * 32 + j * 8 + 2 * lane + 1] = s1;
                    }
                }
                __syncthreads();
                if (tid < 256)
                    g_part[blockIdx.x * 256 + tid] = red[tid] + red[256 + tid];
            }
        }
    }
}

// ===========================================================================
// f-layers + softmax (g reduction fused in)
// ===========================================================================
__global__ void f_kernel(const float* __restrict__ fw1, const float* __restrict__ fb1,
                         const float* __restrict__ fw2, const float* __restrict__ fb2,
                         const float* __restrict__ fw3, const float* __restrict__ fb3,
                         float* __restrict__ out) {
    int b = blockIdx.x;
    int t = threadIdx.x;
    __shared__ float s0[256], s1[256];
    __shared__ float lg[10];

    float gs = 0.f;
#pragma unroll
    for (int k = 0; k < 32; k++) gs += g_part[(b * 32 + k) * 256 + t];
    s0[t] = gs;
    __syncthreads();

    float a = fb1[t];
    for (int c = 0; c < 256; c++) a = fmaf(s0[c], fw1[c * 256 + t], a);
    s1[t] = fmaxf(a, 0.f);
    __syncthreads();

    a = fb2[t];
    for (int c = 0; c < 256; c++) a = fmaf(s1[c], fw2[c * 256 + t], a);
    __syncthreads();
    s0[t] = fmaxf(a, 0.f);
    __syncthreads();

    if (t < 10) {
        float z = fb3[t];
        for (int c = 0; c < 256; c++) z = fmaf(s0[c], fw3[c * 10 + t], z);
        lg[t] = z;
    }
    __syncthreads();
    if (t == 0) {
        float mx = lg[0];
#pragma unroll
        for (int i = 1; i < 10; i++) mx = fmaxf(mx, lg[i]);
        float e[10];
        float ssum = 0.f;
#pragma unroll
        for (int i = 0; i < 10; i++) { e[i] = expf(lg[i] - mx); ssum += e[i]; }
        float inv = 1.0f / ssum;
#pragma unroll
        for (int i = 0; i < 10; i++) out[b * 10 + i] = e[i] * inv;
    }
}

// ===========================================================================
// Launch
// ===========================================================================
extern "C" void kernel_launch(void* const* d_in, const int* in_sizes, int n_in,
                              void* d_out, int out_size) {
    (void)in_sizes; (void)n_in; (void)out_size;
    const float* img = (const float*)d_in[0];
    const float* qst = (const float*)d_in[1];
    const float* cw1 = (const float*)d_in[2];
    const float* cb1 = (const float*)d_in[3];
    const float* bg1 = (const float*)d_in[4];
    const float* bb1 = (const float*)d_in[5];
    const float* cw2 = (const float*)d_in[6];
    const float* cb2 = (const float*)d_in[7];
    const float* bg2 = (const float*)d_in[8];
    const float* bb2 = (const float*)d_in[9];
    const float* cw3 = (const float*)d_in[10];
    const float* cb3 = (const float*)d_in[11];
    const float* bg3 = (const float*)d_in[12];
    const float* bb3 = (const float*)d_in[13];
    const float* cw4 = (const float*)d_in[14];
    const float* cb4 = (const float*)d_in[15];
    const float* bg4 = (const float*)d_in[16];
    const float* bb4 = (const float*)d_in[17];
    const float* gw1 = (const float*)d_in[18];
    const float* gb1 = (const float*)d_in[19];
    const float* gw2 = (const float*)d_in[20];
    const float* gb2 = (const float*)d_in[21];
    const float* gw3 = (const float*)d_in[22];
    const float* gb3 = (const float*)d_in[23];
    const float* gw4 = (const float*)d_in[24];
    const float* gb4 = (const float*)d_in[25];
    const float* fw1 = (const float*)d_in[26];
    const float* fb1 = (const float*)d_in[27];
    const float* fw2 = (const float*)d_in[28];
    const float* fb2 = (const float*)d_in[29];
    const float* fw3 = (const float*)d_in[30];
    const float* fb3 = (const float*)d_in[31];
    float* out = (float*)d_out;

    static bool attr_done = false;
    if (!attr_done) {
        cudaFuncSetAttribute(rn_fused, cudaFuncAttributeMaxDynamicSharedMemorySize, GEMM_SMEM);
        attr_done = true;
    }

    // W prep (independent)
    prep_w_kernel<<<dim3(8, 8, 3), dim3(32, 8)>>>(gw2, gw3, gw4);

    // conv stack (BN finalized in-block from partials, folded into consumer)
    conv_kernel<1, 0><<<3072, 256>>>(img, cw1, cb1, nullptr, nullptr);
    bn_part_kernel<1><<<dim3(24, 16), 256>>>();
    conv_kernel<2, 1><<<768, 256>>>(img, cw2, cb2, bg1, bb1);
    bn_part_kernel<2><<<dim3(24, 16), 256>>>();
    conv_kernel<3, 1><<<192, 256>>>(img, cw3, cb3, bg2, bb2);
    bn_part_kernel<3><<<dim3(24, 16), 256>>>();
    conv_kernel<4, 1><<<48, 256>>>(img, cw4, cb4, bg3, bb3);
    bn_part_kernel<4><<<dim3(24, 16), 256>>>();

    // projections (uv finalizes + folds BN4)
    uv_kernel<<<4096, 256>>>(gw1, bg4, bb4);
    qb_kernel<<<64, 256>>>(qst, gw1, gb1);

    // fused relation MLP (3 layers, 128-row tiles, K-chunk 64, 5-stage ring)
    rn_fused<<<2048, 512, GEMM_SMEM>>>(gb2, gb3, gb4);

    // f-layers (g reduction fused) + softmax
    f_kernel<<<64, 256>>>(fw1, fb1, fw2, fb2, fw3, fb3, out);
}

// round 15
// speedup vs baseline: 1.0280x; 1.0280x over previous
#include <cuda_runtime.h>
#include <cuda_fp16.h>
#include <stdint.h>

// ===========================================================================
// Helpers
// ===========================================================================
__device__ __forceinline__ uint32_t smem_to_u32(const void* p) {
    uint32_t a;
    asm("{ .reg .u64 t; cvta.to.shared.u64 t, %1; cvt.u32.u64 %0, t; }" : "=r"(a) : "l"(p));
    return a;
}
__device__ __forceinline__ void cp_async16(uint32_t saddr, const void* gptr) {
    asm volatile("cp.async.cg.shared.global [%0], [%1], 16;" :: "r"(saddr), "l"(gptr));
}
#define CP_COMMIT() asm volatile("cp.async.commit_group;" ::: "memory")
template <int N>
__device__ __forceinline__ void cp_wait() {
    asm volatile("cp.async.wait_group %0;" :: "n"(N) : "memory");
}

__device__ __forceinline__ void ldx4(uint32_t* r, uint32_t addr) {
    asm volatile("ldmatrix.sync.aligned.m8n8.x4.shared.b16 {%0,%1,%2,%3}, [%4];"
                 : "=r"(r[0]), "=r"(r[1]), "=r"(r[2]), "=r"(r[3]) : "r"(addr));
}
__device__ __forceinline__ void mma16(float* d, const uint32_t* a, const uint32_t* b) {
    asm volatile(
        "mma.sync.aligned.m16n8k16.row.col.f32.f16.f16.f32 "
        "{%0,%1,%2,%3}, {%4,%5,%6,%7}, {%8,%9}, {%0,%1,%2,%3};"
        : "+f"(d[0]), "+f"(d[1]), "+f"(d[2]), "+f"(d[3])
        : "r"(a[0]), "r"(a[1]), "r"(a[2]), "r"(a[3]), "r"(b[0]), "r"(b[1]));
}
__device__ __forceinline__ uint32_t pack2(float a, float b) {
    __half2 h = __floats2half2_rn(a, b);
    return *reinterpret_cast<uint32_t*>(&h);
}

// ===========================================================================
// Scratch (device globals only)
// ===========================================================================
__device__ float g_act1[64 * 24 * 64 * 64];
__device__ float g_act2[64 * 24 * 32 * 32];
__device__ float g_act3[64 * 24 * 16 * 16];
__device__ float g_act4[64 * 24 * 8 * 8];
__device__ float g_bnp[24][16][2];
__device__ float g_u[4096 * 256];
__device__ float g_v[4096 * 256];
__device__ float g_qb[64 * 256];
__device__ __half g_Wt[3][256 * 256];     // W^T fp16, [n][k]
__device__ float g_part[2048 * 256];

// ===========================================================================
// Conv (3x3, stride 2, pad 1) + bias + relu.
// 4 ow x 2 co per thread, vectorized input loads, 3 CTAs/SM.
// FOLD=1: previous layer's BN folded on input load; the per-channel
// scale/shift is finalized IN-BLOCK from the 16-way partials (g_bnp).
// ===========================================================================
template <int L>
__device__ __forceinline__ float* act_buf() {
    if constexpr (L == 1) return g_act1;
    else if constexpr (L == 2) return g_act2;
    else if constexpr (L == 3) return g_act3;
    else return g_act4;
}

template <int L, int FOLD>
__global__ void __launch_bounds__(256, 3) conv_kernel(const float* __restrict__ img,
                                                      const float* __restrict__ w,
                                                      const float* __restrict__ cb,
                                                      const float* __restrict__ bg,
                                                      const float* __restrict__ bb) {
    constexpr int CIN = (L == 1) ? 3 : 24;
    constexpr int H   = 256 >> L;
    constexpr int OH  = 128 >> L;
    constexpr int OQ  = OH / 4;
    constexpr int NW  = 24 * CIN * 9;

    __shared__ float sw[NW];
    __shared__ float ssc[24], ssh[24];
    for (int i = threadIdx.x; i < NW; i += 256) sw[i] = w[i];
    if (FOLD && threadIdx.x < 24) {
        constexpr float NPREV = 64.f * (float)((256 >> L) * (256 >> L));
        int c = threadIdx.x;
        float s = 0.f, s2 = 0.f;
#pragma unroll
        for (int k = 0; k < 16; k++) { s += g_bnp[c][k][0]; s2 += g_bnp[c][k][1]; }
        float m   = s / NPREV;
        float var = s2 / NPREV - m * m;
        float rst = rsqrtf(var + 1e-5f);
        ssc[c] = rst * bg[c];
        ssh[c] = bb[c] - m * rst * bg[c];
    }
    __syncthreads();

    const float* in = (L == 1) ? img : act_buf<L - 1 + (L == 1 ? 1 : 0)>();
    float* out = act_buf<L>();

    int idx = blockIdx.x * 256 + threadIdx.x;
    int ow4 = idx % OQ; idx /= OQ;
    int oh  = idx % OH; idx /= OH;
    int cog = idx % 12; int b = idx / 12;
    if (b >= 64) return;
    const int ow0 = ow4 * 4;
    const int co0 = cog * 2;

    float acc[2][4];
#pragma unroll
    for (int c = 0; c < 2; c++) {
        float bv = cb[co0 + c];
#pragma unroll
        for (int d = 0; d < 4; d++) acc[c][d] = bv;
    }

    const int iw0 = 2 * ow0 - 1;
#pragma unroll
    for (int ci = 0; ci < CIN; ci++) {
        const float* ip = in + ((b * CIN + ci) * H) * H;
        const float sc = FOLD ? ssc[ci] : 1.f;
        const float sh = FOLD ? ssh[ci] : 0.f;
        const float* wb = &sw[(co0 * CIN + ci) * 9];
#pragma unroll
        for (int kh = 0; kh < 3; kh++) {
            int ih = 2 * oh - 1 + kh;
            bool rowok = (ih >= 0);                  // ih < H always holds
            const float* rp = ip + ih * H;
            float x[9];
            if (rowok) {
                float4 va = *reinterpret_cast<const float4*>(rp + iw0 + 1);
                float4 vb = *reinterpret_cast<const float4*>(rp + iw0 + 5);
                x[0] = (ow0 > 0) ? rp[iw0] : 0.f;
                x[1] = va.x; x[2] = va.y; x[3] = va.z; x[4] = va.w;
                x[5] = vb.x; x[6] = vb.y; x[7] = vb.z; x[8] = vb.w;
                if (FOLD) {
                    if (ow0 > 0) x[0] = fmaf(x[0], sc, sh);
#pragma unroll
                    for (int t = 1; t < 9; t++) x[t] = fmaf(x[t], sc, sh);
                }
            } else {
#pragma unroll
                for (int t = 0; t < 9; t++) x[t] = 0.f;
            }
#pragma unroll
            for (int c = 0; c < 2; c++) {
                const float* wp = wb + c * CIN * 9 + kh * 3;
#pragma unroll
                for (int kw = 0; kw < 3; kw++) {
                    float wv = wp[kw];
#pragma unroll
                    for (int d = 0; d < 4; d++)
                        acc[c][d] = fmaf(x[2 * d + kw], wv, acc[c][d]);
                }
            }
        }
    }

#pragma unroll
    for (int c = 0; c < 2; c++) {
        float4 o;
        o.x = fmaxf(acc[c][0], 0.f); o.y = fmaxf(acc[c][1], 0.f);
        o.z = fmaxf(acc[c][2], 0.f); o.w = fmaxf(acc[c][3], 0.f);
        *reinterpret_cast<float4*>(
            &out[((b * 24 + co0 + c) * OH + oh) * OH + ow0]) = o;
    }
}

// ===========================================================================
// BatchNorm partial stats (16-way, fixed order, deterministic)
// ===========================================================================
template <int L>
__global__ void bn_part_kernel() {
    constexpr int HW  = (128 >> L) * (128 >> L);
    constexpr int N   = 64 * HW;
    constexpr int SEG = N / 16;
    const float* y = act_buf<L>();
    int c = blockIdx.x, seg = blockIdx.y, t = threadIdx.x;

    float s = 0.f, s2 = 0.f;
    for (int i = seg * SEG + t; i < (seg + 1) * SEG; i += 256) {
        int b = i / HW;
        int p = i - b * HW;
        float v = y[(b * 24 + c) * HW + p];
        s += v;
        s2 += v * v;
    }
    __shared__ float rs[256], rq[256];
    rs[t] = s;
    rq[t] = s2;
    __syncthreads();
    for (int o = 128; o > 0; o >>= 1) {
        if (t < o) { rs[t] += rs[t + o]; rq[t] += rq[t + o]; }
        __syncthreads();
    }
    if (t == 0) { g_bnp[c][seg][0] = rs[0]; g_bnp[c][seg][1] = rq[0]; }
}

// ===========================================================================
// u/v/qb projections (uv finalizes + folds BN4 in-block)
// ===========================================================================
__global__ void uv_kernel(const float* __restrict__ gw1,
                          const float* __restrict__ bg4,
                          const float* __restrict__ bb4) {
    int bp = blockIdx.x;
    int b  = bp >> 6;
    int p  = bp & 63;
    int t  = threadIdx.x;

    __shared__ float ssc[24], ssh[24];
    __shared__ float o[26];
    if (t < 24) {
        float s = 0.f, s2 = 0.f;
#pragma unroll
        for (int k = 0; k < 16; k++) { s += g_bnp[t][k][0]; s2 += g_bnp[t][k][1]; }
        float m   = s / 4096.f;
        float var = s2 / 4096.f - m * m;
        float rst = rsqrtf(var + 1e-5f);
        ssc[t] = rst * bg4[t];
        ssh[t] = bb4[t] - m * rst * bg4[t];
    }
    __syncthreads();
    if (t < 24) o[t] = fmaf(g_act4[(b * 24 + t) * 64 + p], ssc[t], ssh[t]);
    else if (t == 24) o[24] = (float)(p >> 3);
    else if (t == 25) o[25] = (float)(p & 7);
    __syncthreads();

    float u = 0.f, v = 0.f;
#pragma unroll
    for (int c = 0; c < 26; c++) {
        float oc = o[c];
        u = fmaf(oc, gw1[c * 256 + t], u);
        v = fmaf(oc, gw1[(26 + c) * 256 + t], v);
    }
    g_u[bp * 256 + t] = u;
    g_v[bp * 256 + t] = v;
}

__global__ void qb_kernel(const float* __restrict__ qst,
                          const float* __restrict__ gw1,
                          const float* __restrict__ gb1) {
    int b = blockIdx.x;
    int t = threadIdx.x;
    __shared__ float q[11];
    if (t < 11) q[t] = qst[b * 11 + t];
    __syncthreads();
    float s = gb1[t];
#pragma unroll
    for (int k = 0; k < 11; k++) s = fmaf(q[k], gw1[(52 + k) * 256 + t], s);
    g_qb[b * 256 + t] = s;
}

// ===========================================================================
// W prep: transpose to [n][k], round to fp16
// ===========================================================================
__global__ void prep_w_kernel(const float* __restrict__ w2,
                              const float* __restrict__ w3,
                              const float* __restrict__ w4) {
    __shared__ float tb[32][33];
    int L = blockIdx.z;
    const float* w = (L == 0) ? w2 : (L == 1) ? w3 : w4;
    int kb = blockIdx.y * 32, nb = blockIdx.x * 32;
#pragma unroll
    for (int i = 0; i < 4; i++)
        tb[threadIdx.y + 8 * i][threadIdx.x] = w[(kb + threadIdx.y + 8 * i) * 256 + nb + threadIdx.x];
    __syncthreads();
#pragma unroll
    for (int i = 0; i < 4; i++) {
        int n = nb + threadIdx.y + 8 * i;
        int k = kb + threadIdx.x;
        g_Wt[L][n * 256 + k] = __float2half_rn(tb[threadIdx.x][threadIdx.y + 8 * i]);
    }
}

// ===========================================================================
// FUSED relation MLP (round-13 schedule): 128-row tile, h1 -> h2 -> h3 ->
// column sums. h tile (64KB, fp16, swizzled) updated IN PLACE.
// K-chunk = 64, 4-stage B ring (32KB stages, & 3 indexing), prefetch depth 3,
// wait<=2. CTA: 128 rows x 256 cols, 512 threads (16 warps, 2Mx8N, warp 64x32).
// ===========================================================================
static constexpr int BOFF = 65536, BSTAGE = 32768;          // B ring: 4 x 32KB
static constexpr int GEMM_SMEM = BOFF + 4 * BSTAGE;         // 192KB

__global__ void __launch_bounds__(512, 1) rn_fused(const float* __restrict__ gb2,
                                                   const float* __restrict__ gb3,
                                                   const float* __restrict__ gb4) {
    extern __shared__ char smem[];
    const uint32_t sb = smem_to_u32(smem);

    const int tid  = threadIdx.x;
    const int lane = tid & 31;
    const int wid  = tid >> 5;           // 0..15
    const int g    = lane >> 2;
    const int tig  = lane & 3;
    const int warpM = wid & 1;
    const int warpN = wid >> 1;          // 0..7
    const int m0 = blockIdx.x << 7;

    // ---- per-lane ldmatrix geometry ----
    const int arow16 = lane & 15;
    const int ca = (lane >> 4) & 1;      // k-half (16B)
    const int rxa = lane & 7;            // swizzle phase (row & 7)
    uint32_t rowbA[4];
#pragma unroll
    for (int i = 0; i < 4; i++)
        rowbA[i] = (uint32_t)(warpM * 64 + i * 16 + arow16) * 512;

    uint32_t offB[2][4];
    {
        int rb = (lane & 7) + ((lane >> 4) & 1) * 8;
        int cbs = (lane >> 3) & 1;
#pragma unroll
        for (int jp = 0; jp < 2; jp++)
#pragma unroll
            for (int ks = 0; ks < 4; ks++) {
                int row = warpN * 32 + jp * 16 + rb;
                int ch  = 2 * ks + cbs;
                offB[jp][ks] = BOFF + row * 128 + ((ch ^ (row & 7)) << 4);
            }
    }

    // ---- B prefetch: chunk gidx (64 k's) -> ring stage gidx & 3 ----
    auto issueB = [&](int gidx) {
        int l = gidx >> 2, kt = gidx & 3, st = gidx & 3;
        int row = tid >> 1;              // 0..255
        const __half* src = g_Wt[l] + row * 256 + kt * 64;
        uint32_t dbase = sb + BOFF + st * BSTAGE + row * 128;
        int rsw = row & 7;
#pragma unroll
        for (int cc = 0; cc < 4; cc++) {
            int c = 4 * (tid & 1) + cc;
            cp_async16(dbase + ((c ^ rsw) << 4), src + 8 * c);
        }
        CP_COMMIT();
    };
    issueB(0); issueB(1); issueB(2);

    // ---- build h1 tile (128 rows) while prefetches fly ----
    {
        int row = tid >> 2, kq = tid & 3;
        int rg = m0 + row;
        int b = rg >> 12, ii = (rg >> 6) & 63, jj = rg & 63;
        const float* up = g_u + ((b << 6) + jj) * 256;
        const float* vp = g_v + ((b << 6) + ii) * 256;
        const float* qp = g_qb + (b << 8);
        uint32_t rbase = row * 512;
        int rx = row & 7;
#pragma unroll
        for (int q = 0; q < 8; q++) {
            int s = kq + 4 * q;
            int k0 = s * 8;
            uint32_t ph[4];
#pragma unroll
            for (int h = 0; h < 2; h++) {
                float4 uu = *reinterpret_cast<const float4*>(up + k0 + 4 * h);
                float4 vv = *reinterpret_cast<const float4*>(vp + k0 + 4 * h);
                float4 qq = *reinterpret_cast<const float4*>(qp + k0 + 4 * h);
                float x0 = fmaxf(uu.x + vv.x + qq.x, 0.f);
                float x1 = fmaxf(uu.y + vv.y + qq.y, 0.f);
                float x2 = fmaxf(uu.z + vv.z + qq.z, 0.f);
                float x3 = fmaxf(uu.w + vv.w + qq.w, 0.f);
                ph[2 * h]     = pack2(x0, x1);
                ph[2 * h + 1] = pack2(x2, x3);
            }
            *reinterpret_cast<uint4*>(smem + rbase + ((s ^ rx) << 4)) =
                make_uint4(ph[0], ph[1], ph[2], ph[3]);
        }
    }

    float acc[4][4][4];
    float bz[4][2];
    const float* biases[3] = {gb2, gb3, gb4};

    for (int gidx = 0; gidx < 12; gidx++) {
        const int l  = gidx >> 2;
        const int kt = gidx & 3;
        const int st = gidx & 3;

        if (gidx <= 9) cp_wait<2>();
        else if (gidx == 10) cp_wait<1>();
        else cp_wait<0>();
        __syncthreads();
        if (gidx < 9) issueB(gidx + 3);

        if (kt == 0) {
            const float* bp = biases[l];
#pragma unroll
            for (int j = 0; j < 4; j++) {
                int c = warpN * 32 + j * 8 + 2 * tig;
                bz[j][0] = bp[c];
                bz[j][1] = bp[c + 1];
            }
#pragma unroll
            for (int i = 0; i < 4; i++)
#pragma unroll
                for (int j = 0; j < 4; j++)
#pragma unroll
                    for (int e = 0; e < 4; e++) acc[i][j][e] = 0.f;
        }

        // ---- compute chunk (64 k's = 4 x k16) ----
#pragma unroll
        for (int ks = 0; ks < 4; ks++) {
            uint32_t bf[2][4];
#pragma unroll
            for (int jp = 0; jp < 2; jp++)
                ldx4(bf[jp], sb + st * BSTAGE + offB[jp][ks]);
            const int slot = kt * 8 + ks * 2 + ca;
            const uint32_t soff = (uint32_t)((slot ^ rxa) << 4);
#pragma unroll
            for (int i = 0; i < 4; i++) {
                uint32_t af[4];
                ldx4(af, sb + rowbA[i] + soff);
#pragma unroll
                for (int jp = 0; jp < 2; jp++) {
                    mma16(acc[i][2 * jp],     af, bf[jp]);
                    mma16(acc[i][2 * jp + 1], af, bf[jp] + 2);
                }
            }
        }

        // ---- layer epilogue ----
        if (kt == 3) {
            __syncthreads();   // all reads of this layer's h done before overwrite
            if (l < 2) {
#pragma unroll
                for (int i = 0; i < 4; i++) {
                    int r0 = warpM * 64 + i * 16 + g;
                    int r1 = r0 + 8;
#pragma unroll
                    for (int j = 0; j < 4; j++) {
                        int cbyte = warpN * 64 + j * 16 + tig * 4;
                        int s = cbyte >> 4, off = cbyte & 15;
                        float y00 = fmaxf(acc[i][j][0] + bz[j][0], 0.f);
                        float y01 = fmaxf(acc[i][j][1] + bz[j][1], 0.f);
                        float y10 = fmaxf(acc[i][j][2] + bz[j][0], 0.f);
                        float y11 = fmaxf(acc[i][j][3] + bz[j][1], 0.f);
                        *reinterpret_cast<uint32_t*>(
                            smem + r0 * 512 + ((s ^ (r0 & 7)) << 4) + off) =
                            pack2(y00, y01);
                        *reinterpret_cast<uint32_t*>(
                            smem + r1 * 512 + ((s ^ (r1 & 7)) << 4) + off) =
                            pack2(y10, y11);
                    }
                }
                // next chunk's syncthreads orders these writes before reads
            } else {
                // final layer: fused 128-row column sums -> g_part
                float* red = reinterpret_cast<float*>(smem);  // h tile dead
#pragma unroll
                for (int j = 0; j < 4; j++) {
                    float s0 = 0.f, s1 = 0.f;
#pragma unroll
                    for (int i = 0; i < 4; i++) {
                        s0 += fmaxf(acc[i][j][0] + bz[j][0], 0.f) +
                              fmaxf(acc[i][j][2] + bz[j][0], 0.f);
                        s1 += fmaxf(acc[i][j][1] + bz[j][1], 0.f) +
                              fmaxf(acc[i][j][3] + bz[j][1], 0.f);
                    }
#pragma unroll
                    for (int m = 4; m <= 16; m <<= 1) {
                        s0 += __shfl_xor_sync(0xffffffffu, s0, m);
                        s1 += __shfl_xor_sync(0xffffffffu, s1, m);
                    }
                    if (lane < 4) {
                        red[warpM * 256 + warpN * 32 + j * 8 + 2 * lane]     = s0;
                        red[warpM * 256 + warpN * 32 + j * 8 + 2 * lane + 1] = s1;
                    }
                }
                __syncthreads();
                if (tid < 256)
                    g_part[blockIdx.x * 256 + tid] = red[tid] + red[256 + tid];
            }
        }
    }
}

// ===========================================================================
// f-layers + softmax (g reduction fused in)
// ===========================================================================
__global__ void f_kernel(const float* __restrict__ fw1, const float* __restrict__ fb1,
                         const float* __restrict__ fw2, const float* __restrict__ fb2,
                         const float* __restrict__ fw3, const float* __restrict__ fb3,
                         float* __restrict__ out) {
    int b = blockIdx.x;
    int t = threadIdx.x;
    __shared__ float s0[256], s1[256];
    __shared__ float lg[10];

    float gs = 0.f;
#pragma unroll
    for (int k = 0; k < 32; k++) gs += g_part[(b * 32 + k) * 256 + t];
    s0[t] = gs;
    __syncthreads();

    float a = fb1[t];
    for (int c = 0; c < 256; c++) a = fmaf(s0[c], fw1[c * 256 + t], a);
    s1[t] = fmaxf(a, 0.f);
    __syncthreads();

    a = fb2[t];
    for (int c = 0; c < 256; c++) a = fmaf(s1[c], fw2[c * 256 + t], a);
    __syncthreads();
    s0[t] = fmaxf(a, 0.f);
    __syncthreads();

    if (t < 10) {
        float z = fb3[t];
        for (int c = 0; c < 256; c++) z = fmaf(s0[c], fw3[c * 10 + t], z);
        lg[t] = z;
    }
    __syncthreads();
    if (t == 0) {
        float mx = lg[0];
#pragma unroll
        for (int i = 1; i < 10; i++) mx = fmaxf(mx, lg[i]);
        float e[10];
        float ssum = 0.f;
#pragma unroll
        for (int i = 0; i < 10; i++) { e[i] = expf(lg[i] - mx); ssum += e[i]; }
        float inv = 1.0f / ssum;
#pragma unroll
        for (int i = 0; i < 10; i++) out[b * 10 + i] = e[i] * inv;
    }
}

// ===========================================================================
// Launch
// ===========================================================================
extern "C" void kernel_launch(void* const* d_in, const int* in_sizes, int n_in,
                              void* d_out, int out_size) {
    (void)in_sizes; (void)n_in; (void)out_size;
    const float* img = (const float*)d_in[0];
    const float* qst = (const float*)d_in[1];
    const float* cw1 = (const float*)d_in[2];
    const float* cb1 = (const float*)d_in[3];
    const float* bg1 = (const float*)d_in[4];
    const float* bb1 = (const float*)d_in[5];
    const float* cw2 = (const float*)d_in[6];
    const float* cb2 = (const float*)d_in[7];
    const float* bg2 = (const float*)d_in[8];
    const float* bb2 = (const float*)d_in[9];
    const float* cw3 = (const float*)d_in[10];
    const float* cb3 = (const float*)d_in[11];
    const float* bg3 = (const float*)d_in[12];
    const float* bb3 = (const float*)d_in[13];
    const float* cw4 = (const float*)d_in[14];
    const float* cb4 = (const float*)d_in[15];
    const float* bg4 = (const float*)d_in[16];
    const float* bb4 = (const float*)d_in[17];
    const float* gw1 = (const float*)d_in[18];
    const float* gb1 = (const float*)d_in[19];
    const float* gw2 = (const float*)d_in[20];
    const float* gb2 = (const float*)d_in[21];
    const float* gw3 = (const float*)d_in[22];
    const float* gb3 = (const float*)d_in[23];
    const float* gw4 = (const float*)d_in[24];
    const float* gb4 = (const float*)d_in[25];
    const float* fw1 = (const float*)d_in[26];
    const float* fb1 = (const float*)d_in[27];
    const float* fw2 = (const float*)d_in[28];
    const float* fb2 = (const float*)d_in[29];
    const float* fw3 = (const float*)d_in[30];
    const float* fb3 = (const float*)d_in[31];
    float* out = (float*)d_out;

    static bool attr_done = false;
    if (!attr_done) {
        cudaFuncSetAttribute(rn_fused, cudaFuncAttributeMaxDynamicSharedMemorySize, GEMM_SMEM);
        attr_done = true;
    }

    // W prep (independent)
    prep_w_kernel<<<dim3(8, 8, 3), dim3(32, 8)>>>(gw2, gw3, gw4);

    // conv stack (BN finalized in-block from partials, folded into consumer)
    conv_kernel<1, 0><<<3072, 256>>>(img, cw1, cb1, nullptr, nullptr);
    bn_part_kernel<1><<<dim3(24, 16), 256>>>();
    conv_kernel<2, 1><<<768, 256>>>(img, cw2, cb2, bg1, bb1);
    bn_part_kernel<2><<<dim3(24, 16), 256>>>();
    conv_kernel<3, 1><<<192, 256>>>(img, cw3, cb3, bg2, bb2);
    bn_part_kernel<3><<<dim3(24, 16), 256>>>();
    conv_kernel<4, 1><<<48, 256>>>(img, cw4, cb4, bg3, bb3);
    bn_part_kernel<4><<<dim3(24, 16), 256>>>();

    // projections (uv finalizes + folds BN4)
    uv_kernel<<<4096, 256>>>(gw1, bg4, bb4);
    qb_kernel<<<64, 256>>>(qst, gw1, gb1);

    // fused relation MLP (3 layers, 128-row tiles, K-chunk 64, 4-stage ring)
    rn_fused<<<2048, 512, GEMM_SMEM>>>(gb2, gb3, gb4);

    // f-layers (g reduction fused) + softmax
    f_kernel<<<64, 256>>>(fw1, fb1, fw2, fb2, fw3, fb3, out);
}

// round 16
// speedup vs baseline: 1.0818x; 1.0523x over previous
#include <cuda_runtime.h>
#include <cuda_fp16.h>
#include <stdint.h>

// ===========================================================================
// Helpers
// ===========================================================================
__device__ __forceinline__ uint32_t smem_to_u32(const void* p) {
    uint32_t a;
    asm("{ .reg .u64 t; cvta.to.shared.u64 t, %1; cvt.u32.u64 %0, t; }" : "=r"(a) : "l"(p));
    return a;
}
__device__ __forceinline__ void cp_async16(uint32_t saddr, const void* gptr) {
    asm volatile("cp.async.cg.shared.global [%0], [%1], 16;" :: "r"(saddr), "l"(gptr));
}
#define CP_COMMIT() asm volatile("cp.async.commit_group;" ::: "memory")
template <int N>
__device__ __forceinline__ void cp_wait() {
    asm volatile("cp.async.wait_group %0;" :: "n"(N) : "memory");
}

__device__ __forceinline__ void ldx4(uint32_t* r, uint32_t addr) {
    asm volatile("ldmatrix.sync.aligned.m8n8.x4.shared.b16 {%0,%1,%2,%3}, [%4];"
                 : "=r"(r[0]), "=r"(r[1]), "=r"(r[2]), "=r"(r[3]) : "r"(addr));
}
__device__ __forceinline__ void mma16(float* d, const uint32_t* a, const uint32_t* b) {
    asm volatile(
        "mma.sync.aligned.m16n8k16.row.col.f32.f16.f16.f32 "
        "{%0,%1,%2,%3}, {%4,%5,%6,%7}, {%8,%9}, {%0,%1,%2,%3};"
        : "+f"(d[0]), "+f"(d[1]), "+f"(d[2]), "+f"(d[3])
        : "r"(a[0]), "r"(a[1]), "r"(a[2]), "r"(a[3]), "r"(b[0]), "r"(b[1]));
}
__device__ __forceinline__ uint32_t pack2(float a, float b) {
    __half2 h = __floats2half2_rn(a, b);
    return *reinterpret_cast<uint32_t*>(&h);
}

// ===========================================================================
// Scratch (device globals only)
// ===========================================================================
__device__ float g_act1[64 * 24 * 64 * 64];
__device__ float g_act2[64 * 24 * 32 * 32];
__device__ float g_act3[64 * 24 * 16 * 16];
__device__ float g_act4[64 * 24 * 8 * 8];
__device__ float g_bnp[24][16][2];
__device__ float g_u[4096 * 256];
__device__ float g_v[4096 * 256];
__device__ float g_qb[64 * 256];
__device__ __half g_Wt[3][256 * 256];     // W^T fp16, [n][k]
__device__ float g_part[2048 * 256];

// ===========================================================================
// Conv (3x3, stride 2, pad 1) + bias + relu.   4 ow x 4 co per thread.
// FOLD=1: previous layer's BN is folded into the WEIGHTS (sw *= sc[ci]) and
// the Σ w·sh term goes into the bias with exact border corrections
// (kh=0 taps absent iff oh==0; kw=0 taps absent iff ow==0).
// Hot loop is pure loads+FMA. 4 CTAs/SM.
// ===========================================================================
template <int L>
__device__ __forceinline__ float* act_buf() {
    if constexpr (L == 1) return g_act1;
    else if constexpr (L == 2) return g_act2;
    else if constexpr (L == 3) return g_act3;
    else return g_act4;
}

template <int L, int FOLD>
__global__ void __launch_bounds__(256, 4) conv_kernel(const float* __restrict__ img,
                                                      const float* __restrict__ w,
                                                      const float* __restrict__ cb,
                                                      const float* __restrict__ bg,
                                                      const float* __restrict__ bb) {
    constexpr int CIN = (L == 1) ? 3 : 24;
    constexpr int H   = 256 >> L;
    constexpr int OH  = 128 >> L;
    constexpr int OQ  = OH / 4;
    constexpr int NW  = 24 * CIN * 9;

    __shared__ float sw[NW];
    __shared__ float ssc[24], ssh[24];
    __shared__ float sful[24], skh0[24], skw0[24], s00[24];

    for (int i = threadIdx.x; i < NW; i += 256) sw[i] = w[i];
    if (FOLD && threadIdx.x < 24) {
        constexpr float NPREV = 64.f * (float)((256 >> L) * (256 >> L));
        int c = threadIdx.x;
        float s = 0.f, s2 = 0.f;
#pragma unroll
        for (int k = 0; k < 16; k++) { s += g_bnp[c][k][0]; s2 += g_bnp[c][k][1]; }
        float m   = s / NPREV;
        float var = s2 / NPREV - m * m;
        float rst = rsqrtf(var + 1e-5f);
        ssc[c] = rst * bg[c];
        ssh[c] = bb[c] - m * rst * bg[c];
    }
    __syncthreads();
    if (FOLD) {
        if (threadIdx.x < 24) {
            int co = threadIdx.x;
            float f = 0.f, h0 = 0.f, w0 = 0.f, c00 = 0.f;
            for (int ci = 0; ci < CIN; ci++) {
                const float* wp = &sw[(co * CIN + ci) * 9];
                float sh = ssh[ci];
                float r0 = wp[0] + wp[1] + wp[2];
                float al = r0 + wp[3] + wp[4] + wp[5] + wp[6] + wp[7] + wp[8];
                float cl = wp[0] + wp[3] + wp[6];
                f  = fmaf(sh, al, f);
                h0 = fmaf(sh, r0, h0);
                w0 = fmaf(sh, cl, w0);
                c00 = fmaf(sh, wp[0], c00);
            }
            sful[co] = f; skh0[co] = h0; skw0[co] = w0; s00[co] = c00;
        }
        __syncthreads();
        for (int i = threadIdx.x; i < NW; i += 256)
            sw[i] *= ssc[(i / 9) % CIN];
        __syncthreads();
    } else {
        __syncthreads();
    }

    const float* in = (L == 1) ? img : act_buf<L - 1 + (L == 1 ? 1 : 0)>();
    float* out = act_buf<L>();

    int idx = blockIdx.x * 256 + threadIdx.x;
    int ow4 = idx % OQ; idx /= OQ;
    int oh  = idx % OH; idx /= OH;
    int cog = idx % 6;  int b = idx / 6;
    if (b >= 64) return;
    const int ow0 = ow4 * 4;
    const int co0 = cog * 4;

    float acc[4][4];
#pragma unroll
    for (int c = 0; c < 4; c++) {
        float base = cb[co0 + c];
        if (FOLD) {
            base += sful[co0 + c];
            if (oh == 0) base -= skh0[co0 + c];
        }
#pragma unroll
        for (int d = 0; d < 4; d++) acc[c][d] = base;
        if (FOLD && ow0 == 0)
            acc[c][0] -= skw0[co0 + c] - ((oh == 0) ? s00[co0 + c] : 0.f);
    }

    const int iw0 = 2 * ow0 - 1;
#pragma unroll
    for (int ci = 0; ci < CIN; ci++) {
        const float* ip = in + ((b * CIN + ci) * H) * H;
        const float* wb = &sw[(co0 * CIN + ci) * 9];
#pragma unroll
        for (int kh = 0; kh < 3; kh++) {
            int ih = 2 * oh - 1 + kh;
            bool rowok = (ih >= 0);                  // ih < H always holds
            const float* rp = ip + ih * H;
            float x[9];
            if (rowok) {
                float4 va = *reinterpret_cast<const float4*>(rp + iw0 + 1);
                float4 vb = *reinterpret_cast<const float4*>(rp + iw0 + 5);
                x[0] = (ow0 > 0) ? rp[iw0] : 0.f;
                x[1] = va.x; x[2] = va.y; x[3] = va.z; x[4] = va.w;
                x[5] = vb.x; x[6] = vb.y; x[7] = vb.z; x[8] = vb.w;
            } else {
#pragma unroll
                for (int t = 0; t < 9; t++) x[t] = 0.f;
            }
#pragma unroll
            for (int c = 0; c < 4; c++) {
                const float* wp = wb + c * CIN * 9 + kh * 3;
#pragma unroll
                for (int kw = 0; kw < 3; kw++) {
                    float wv = wp[kw];
#pragma unroll
                    for (int d = 0; d < 4; d++)
                        acc[c][d] = fmaf(x[2 * d + kw], wv, acc[c][d]);
                }
            }
        }
    }

#pragma unroll
    for (int c = 0; c < 4; c++) {
        float4 o;
        o.x = fmaxf(acc[c][0], 0.f); o.y = fmaxf(acc[c][1], 0.f);
        o.z = fmaxf(acc[c][2], 0.f); o.w = fmaxf(acc[c][3], 0.f);
        *reinterpret_cast<float4*>(
            &out[((b * 24 + co0 + c) * OH + oh) * OH + ow0]) = o;
    }
}

// ===========================================================================
// BatchNorm partial stats (16-way, fixed order, deterministic)
// ===========================================================================
template <int L>
__global__ void bn_part_kernel() {
    constexpr int HW  = (128 >> L) * (128 >> L);
    constexpr int N   = 64 * HW;
    constexpr int SEG = N / 16;
    const float* y = act_buf<L>();
    int c = blockIdx.x, seg = blockIdx.y, t = threadIdx.x;

    float s = 0.f, s2 = 0.f;
    for (int i = seg * SEG + t; i < (seg + 1) * SEG; i += 256) {
        int b = i / HW;
        int p = i - b * HW;
        float v = y[(b * 24 + c) * HW + p];
        s += v;
        s2 += v * v;
    }
    __shared__ float rs[256], rq[256];
    rs[t] = s;
    rq[t] = s2;
    __syncthreads();
    for (int o = 128; o > 0; o >>= 1) {
        if (t < o) { rs[t] += rs[t + o]; rq[t] += rq[t + o]; }
        __syncthreads();
    }
    if (t == 0) { g_bnp[c][seg][0] = rs[0]; g_bnp[c][seg][1] = rq[0]; }
}

// ===========================================================================
// u/v/qb projections (uv finalizes + folds BN4 in-block)
// ===========================================================================
__global__ void uv_kernel(const float* __restrict__ gw1,
                          const float* __restrict__ bg4,
                          const float* __restrict__ bb4) {
    int bp = blockIdx.x;
    int b  = bp >> 6;
    int p  = bp & 63;
    int t  = threadIdx.x;

    __shared__ float ssc[24], ssh[24];
    __shared__ float o[26];
    if (t < 24) {
        float s = 0.f, s2 = 0.f;
#pragma unroll
        for (int k = 0; k < 16; k++) { s += g_bnp[t][k][0]; s2 += g_bnp[t][k][1]; }
        float m   = s / 4096.f;
        float var = s2 / 4096.f - m * m;
        float rst = rsqrtf(var + 1e-5f);
        ssc[t] = rst * bg4[t];
        ssh[t] = bb4[t] - m * rst * bg4[t];
    }
    __syncthreads();
    if (t < 24) o[t] = fmaf(g_act4[(b * 24 + t) * 64 + p], ssc[t], ssh[t]);
    else if (t == 24) o[24] = (float)(p >> 3);
    else if (t == 25) o[25] = (float)(p & 7);
    __syncthreads();

    float u = 0.f, v = 0.f;
#pragma unroll
    for (int c = 0; c < 26; c++) {
        float oc = o[c];
        u = fmaf(oc, gw1[c * 256 + t], u);
        v = fmaf(oc, gw1[(26 + c) * 256 + t], v);
    }
    g_u[bp * 256 + t] = u;
    g_v[bp * 256 + t] = v;
}

__global__ void qb_kernel(const float* __restrict__ qst,
                          const float* __restrict__ gw1,
                          const float* __restrict__ gb1) {
    int b = blockIdx.x;
    int t = threadIdx.x;
    __shared__ float q[11];
    if (t < 11) q[t] = qst[b * 11 + t];
    __syncthreads();
    float s = gb1[t];
#pragma unroll
    for (int k = 0; k < 11; k++) s = fmaf(q[k], gw1[(52 + k) * 256 + t], s);
    g_qb[b * 256 + t] = s;
}

// ===========================================================================
// W prep: transpose to [n][k], round to fp16
// ===========================================================================
__global__ void prep_w_kernel(const float* __restrict__ w2,
                              const float* __restrict__ w3,
                              const float* __restrict__ w4) {
    __shared__ float tb[32][33];
    int L = blockIdx.z;
    const float* w = (L == 0) ? w2 : (L == 1) ? w3 : w4;
    int kb = blockIdx.y * 32, nb = blockIdx.x * 32;
#pragma unroll
    for (int i = 0; i < 4; i++)
        tb[threadIdx.y + 8 * i][threadIdx.x] = w[(kb + threadIdx.y + 8 * i) * 256 + nb + threadIdx.x];
    __syncthreads();
#pragma unroll
    for (int i = 0; i < 4; i++) {
        int n = nb + threadIdx.y + 8 * i;
        int k = kb + threadIdx.x;
        g_Wt[L][n * 256 + k] = __float2half_rn(tb[threadIdx.x][threadIdx.y + 8 * i]);
    }
}

// ===========================================================================
// FUSED relation MLP (round-13 schedule): 128-row tile, h1 -> h2 -> h3 ->
// column sums. h tile (64KB, fp16, swizzled) updated IN PLACE.
// K-chunk = 64, 4-stage B ring (32KB stages, & 3 indexing), prefetch depth 3,
// wait<=2. CTA: 128 rows x 256 cols, 512 threads (16 warps, 2Mx8N, warp 64x32).
// ===========================================================================
static constexpr int BOFF = 65536, BSTAGE = 32768;          // B ring: 4 x 32KB
static constexpr int GEMM_SMEM = BOFF + 4 * BSTAGE;         // 192KB

__global__ void __launch_bounds__(512, 1) rn_fused(const float* __restrict__ gb2,
                                                   const float* __restrict__ gb3,
                                                   const float* __restrict__ gb4) {
    extern __shared__ char smem[];
    const uint32_t sb = smem_to_u32(smem);

    const int tid  = threadIdx.x;
    const int lane = tid & 31;
    const int wid  = tid >> 5;           // 0..15
    const int g    = lane >> 2;
    const int tig  = lane & 3;
    const int warpM = wid & 1;
    const int warpN = wid >> 1;          // 0..7
    const int m0 = blockIdx.x << 7;

    // ---- per-lane ldmatrix geometry ----
    const int arow16 = lane & 15;
    const int ca = (lane >> 4) & 1;      // k-half (16B)
    const int rxa = lane & 7;            // swizzle phase (row & 7)
    uint32_t rowbA[4];
#pragma unroll
    for (int i = 0; i < 4; i++)
        rowbA[i] = (uint32_t)(warpM * 64 + i * 16 + arow16) * 512;

    uint32_t offB[2][4];
    {
        int rb = (lane & 7) + ((lane >> 4) & 1) * 8;
        int cbs = (lane >> 3) & 1;
#pragma unroll
        for (int jp = 0; jp < 2; jp++)
#pragma unroll
            for (int ks = 0; ks < 4; ks++) {
                int row = warpN * 32 + jp * 16 + rb;
                int ch  = 2 * ks + cbs;
                offB[jp][ks] = BOFF + row * 128 + ((ch ^ (row & 7)) << 4);
            }
    }

    // ---- B prefetch: chunk gidx (64 k's) -> ring stage gidx & 3 ----
    auto issueB = [&](int gidx) {
        int l = gidx >> 2, kt = gidx & 3, st = gidx & 3;
        int row = tid >> 1;              // 0..255
        const __half* src = g_Wt[l] + row * 256 + kt * 64;
        uint32_t dbase = sb + BOFF + st * BSTAGE + row * 128;
        int rsw = row & 7;
#pragma unroll
        for (int cc = 0; cc < 4; cc++) {
            int c = 4 * (tid & 1) + cc;
            cp_async16(dbase + ((c ^ rsw) << 4), src + 8 * c);
        }
        CP_COMMIT();
    };
    issueB(0); issueB(1); issueB(2);

    // ---- build h1 tile (128 rows) while prefetches fly ----
    {
        int row = tid >> 2, kq = tid & 3;
        int rg = m0 + row;
        int b = rg >> 12, ii = (rg >> 6) & 63, jj = rg & 63;
        const float* up = g_u + ((b << 6) + jj) * 256;
        const float* vp = g_v + ((b << 6) + ii) * 256;
        const float* qp = g_qb + (b << 8);
        uint32_t rbase = row * 512;
        int rx = row & 7;
#pragma unroll
        for (int q = 0; q < 8; q++) {
            int s = kq + 4 * q;
            int k0 = s * 8;
            uint32_t ph[4];
#pragma unroll
            for (int h = 0; h < 2; h++) {
                float4 uu = *reinterpret_cast<const float4*>(up + k0 + 4 * h);
                float4 vv = *reinterpret_cast<const float4*>(vp + k0 + 4 * h);
                float4 qq = *reinterpret_cast<const float4*>(qp + k0 + 4 * h);
                float x0 = fmaxf(uu.x + vv.x + qq.x, 0.f);
                float x1 = fmaxf(uu.y + vv.y + qq.y, 0.f);
                float x2 = fmaxf(uu.z + vv.z + qq.z, 0.f);
                float x3 = fmaxf(uu.w + vv.w + qq.w, 0.f);
                ph[2 * h]     = pack2(x0, x1);
                ph[2 * h + 1] = pack2(x2, x3);
            }
            *reinterpret_cast<uint4*>(smem + rbase + ((s ^ rx) << 4)) =
                make_uint4(ph[0], ph[1], ph[2], ph[3]);
        }
    }

    float acc[4][4][4];
    float bz[4][2];
    const float* biases[3] = {gb2, gb3, gb4};

    for (int gidx = 0; gidx < 12; gidx++) {
        const int l  = gidx >> 2;
        const int kt = gidx & 3;
        const int st = gidx & 3;

        if (gidx <= 9) cp_wait<2>();
        else if (gidx == 10) cp_wait<1>();
        else cp_wait<0>();
        __syncthreads();
        if (gidx < 9) issueB(gidx + 3);

        if (kt == 0) {
            const float* bp = biases[l];
#pragma unroll
            for (int j = 0; j < 4; j++) {
                int c = warpN * 32 + j * 8 + 2 * tig;
                bz[j][0] = bp[c];
                bz[j][1] = bp[c + 1];
            }
#pragma unroll
            for (int i = 0; i < 4; i++)
#pragma unroll
                for (int j = 0; j < 4; j++)
#pragma unroll
                    for (int e = 0; e < 4; e++) acc[i][j][e] = 0.f;
        }

        // ---- compute chunk (64 k's = 4 x k16) ----
#pragma unroll
        for (int ks = 0; ks < 4; ks++) {
            uint32_t bf[2][4];
#pragma unroll
            for (int jp = 0; jp < 2; jp++)
                ldx4(bf[jp], sb + st * BSTAGE + offB[jp][ks]);
            const int slot = kt * 8 + ks * 2 + ca;
            const uint32_t soff = (uint32_t)((slot ^ rxa) << 4);
#pragma unroll
            for (int i = 0; i < 4; i++) {
                uint32_t af[4];
                ldx4(af, sb + rowbA[i] + soff);
#pragma unroll
                for (int jp = 0; jp < 2; jp++) {
                    mma16(acc[i][2 * jp],     af, bf[jp]);
                    mma16(acc[i][2 * jp + 1], af, bf[jp] + 2);
                }
            }
        }

        // ---- layer epilogue ----
        if (kt == 3) {
            __syncthreads();   // all reads of this layer's h done before overwrite
            if (l < 2) {
#pragma unroll
                for (int i = 0; i < 4; i++) {
                    int r0 = warpM * 64 + i * 16 + g;
                    int r1 = r0 + 8;
#pragma unroll
                    for (int j = 0; j < 4; j++) {
                        int cbyte = warpN * 64 + j * 16 + tig * 4;
                        int s = cbyte >> 4, off = cbyte & 15;
                        float y00 = fmaxf(acc[i][j][0] + bz[j][0], 0.f);
                        float y01 = fmaxf(acc[i][j][1] + bz[j][1], 0.f);
                        float y10 = fmaxf(acc[i][j][2] + bz[j][0], 0.f);
                        float y11 = fmaxf(acc[i][j][3] + bz[j][1], 0.f);
                        *reinterpret_cast<uint32_t*>(
                            smem + r0 * 512 + ((s ^ (r0 & 7)) << 4) + off) =
                            pack2(y00, y01);
                        *reinterpret_cast<uint32_t*>(
                            smem + r1 * 512 + ((s ^ (r1 & 7)) << 4) + off) =
                            pack2(y10, y11);
                    }
                }
                // next chunk's syncthreads orders these writes before reads
            } else {
                // final layer: fused 128-row column sums -> g_part
                float* red = reinterpret_cast<float*>(smem);  // h tile dead
#pragma unroll
                for (int j = 0; j < 4; j++) {
                    float s0 = 0.f, s1 = 0.f;
#pragma unroll
                    for (int i = 0; i < 4; i++) {
                        s0 += fmaxf(acc[i][j][0] + bz[j][0], 0.f) +
                              fmaxf(acc[i][j][2] + bz[j][0], 0.f);
                        s1 += fmaxf(acc[i][j][1] + bz[j][1], 0.f) +
                              fmaxf(acc[i][j][3] + bz[j][1], 0.f);
                    }
#pragma unroll
                    for (int m = 4; m <= 16; m <<= 1) {
                        s0 += __shfl_xor_sync(0xffffffffu, s0, m);
                        s1 += __shfl_xor_sync(0xffffffffu, s1, m);
                    }
                    if (lane < 4) {
                        red[warpM * 256 + warpN * 32 + j * 8 + 2 * lane]     = s0;
                        red[warpM * 256 + warpN * 32 + j * 8 + 2 * lane + 1] = s1;
                    }
                }
                __syncthreads();
                if (tid < 256)
                    g_part[blockIdx.x * 256 + tid] = red[tid] + red[256 + tid];
            }
        }
    }
}

// ===========================================================================
// f-layers + softmax (g reduction fused in)
// ===========================================================================
__global__ void f_kernel(const float* __restrict__ fw1, const float* __restrict__ fb1,
                         const float* __restrict__ fw2, const float* __restrict__ fb2,
                         const float* __restrict__ fw3, const float* __restrict__ fb3,
                         float* __restrict__ out) {
    int b = blockIdx.x;
    int t = threadIdx.x;
    __shared__ float s0[256], s1[256];
    __shared__ float lg[10];

    float gs = 0.f;
#pragma unroll
    for (int k = 0; k < 32; k++) gs += g_part[(b * 32 + k) * 256 + t];
    s0[t] = gs;
    __syncthreads();

    float a = fb1[t];
    for (int c = 0; c < 256; c++) a = fmaf(s0[c], fw1[c * 256 + t], a);
    s1[t] = fmaxf(a, 0.f);
    __syncthreads();

    a = fb2[t];
    for (int c = 0; c < 256; c++) a = fmaf(s1[c], fw2[c * 256 + t], a);
    __syncthreads();
    s0[t] = fmaxf(a, 0.f);
    __syncthreads();

    if (t < 10) {
        float z = fb3[t];
        for (int c = 0; c < 256; c++) z = fmaf(s0[c], fw3[c * 10 + t], z);
        lg[t] = z;
    }
    __syncthreads();
    if (t == 0) {
        float mx = lg[0];
#pragma unroll
        for (int i = 1; i < 10; i++) mx = fmaxf(mx, lg[i]);
        float e[10];
        float ssum = 0.f;
#pragma unroll
        for (int i = 0; i < 10; i++) { e[i] = expf(lg[i] - mx); ssum += e[i]; }
        float inv = 1.0f / ssum;
#pragma unroll
        for (int i = 0; i < 10; i++) out[b * 10 + i] = e[i] * inv;
    }
}

// ===========================================================================
// Launch
// ===========================================================================
extern "C" void kernel_launch(void* const* d_in, const int* in_sizes, int n_in,
                              void* d_out, int out_size) {
    (void)in_sizes; (void)n_in; (void)out_size;
    const float* img = (const float*)d_in[0];
    const float* qst = (const float*)d_in[1];
    const float* cw1 = (const float*)d_in[2];
    const float* cb1 = (const float*)d_in[3];
    const float* bg1 = (const float*)d_in[4];
    const float* bb1 = (const float*)d_in[5];
    const float* cw2 = (const float*)d_in[6];
    const float* cb2 = (const float*)d_in[7];
    const float* bg2 = (const float*)d_in[8];
    const float* bb2 = (const float*)d_in[9];
    const float* cw3 = (const float*)d_in[10];
    const float* cb3 = (const float*)d_in[11];
    const float* bg3 = (const float*)d_in[12];
    const float* bb3 = (const float*)d_in[13];
    const float* cw4 = (const float*)d_in[14];
    const float* cb4 = (const float*)d_in[15];
    const float* bg4 = (const float*)d_in[16];
    const float* bb4 = (const float*)d_in[17];
    const float* gw1 = (const float*)d_in[18];
    const float* gb1 = (const float*)d_in[19];
    const float* gw2 = (const float*)d_in[20];
    const float* gb2 = (const float*)d_in[21];
    const float* gw3 = (const float*)d_in[22];
    const float* gb3 = (const float*)d_in[23];
    const float* gw4 = (const float*)d_in[24];
    const float* gb4 = (const float*)d_in[25];
    const float* fw1 = (const float*)d_in[26];
    const float* fb1 = (const float*)d_in[27];
    const float* fw2 = (const float*)d_in[28];
    const float* fb2 = (const float*)d_in[29];
    const float* fw3 = (const float*)d_in[30];
    const float* fb3 = (const float*)d_in[31];
    float* out = (float*)d_out;

    static bool attr_done = false;
    if (!attr_done) {
        cudaFuncSetAttribute(rn_fused, cudaFuncAttributeMaxDynamicSharedMemorySize, GEMM_SMEM);
        attr_done = true;
    }

    // W prep (independent)
    prep_w_kernel<<<dim3(8, 8, 3), dim3(32, 8)>>>(gw2, gw3, gw4);

    // conv stack (BN folded into weights+bias; stats finalized in-block)
    conv_kernel<1, 0><<<1536, 256>>>(img, cw1, cb1, nullptr, nullptr);
    bn_part_kernel<1><<<dim3(24, 16), 256>>>();
    conv_kernel<2, 1><<<384, 256>>>(img, cw2, cb2, bg1, bb1);
    bn_part_kernel<2><<<dim3(24, 16), 256>>>();
    conv_kernel<3, 1><<<96, 256>>>(img, cw3, cb3, bg2, bb2);
    bn_part_kernel<3><<<dim3(24, 16), 256>>>();
    conv_kernel<4, 1><<<24, 256>>>(img, cw4, cb4, bg3, bb3);
    bn_part_kernel<4><<<dim3(24, 16), 256>>>();

    // projections (uv finalizes + folds BN4)
    uv_kernel<<<4096, 256>>>(gw1, bg4, bb4);
    qb_kernel<<<64, 256>>>(qst, gw1, gb1);

    // fused relation MLP (3 layers, 128-row tiles, K-chunk 64, 4-stage ring)
    rn_fused<<<2048, 512, GEMM_SMEM>>>(gb2, gb3, gb4);

    // f-layers (g reduction fused) + softmax
    f_kernel<<<64, 256>>>(fw1, fb1, fw2, fb2, fw3, fb3, out);
}